// round 13
// baseline (speedup 1.0000x reference)
#include <cuda_runtime.h>
#include <cuda_fp16.h>
#include <cuda_bf16.h>

#define NU 100000
#define NI 50000
#define NN 150000
#define HD 128
#define NE 1000000
#define NE2 2000000
#define NL 3
#define MAXT 512
#define SLOPE 0.2f
#define OW 512

// As 128*136*2 + Bs 64*136*2 + bias 128*4 + ssm 256*4
#define FUSED_SMEM (34816 + 17408 + 512 + 1024)

// ---------- device scratch ----------
__device__ int    g_deg[NN];
__device__ int    g_rp[NN + 1];
__device__ int    g_cursor[NN];
__device__ float  g_dinv[NN];
__device__ int2   g_edge2[NE2];
__device__ __half g_xhA[NN * HD];   // x buffer, parity 0
__device__ __half g_xhB[NN * HD];   // x buffer, parity 1
__device__ __half g_Th[NN * HD];    // time aggregation (fp16)
__device__ __half g_tth[MAXT * HD]; // fp16 time table
__device__ __half g_Wh[NL * HD * HD];

// ---------- mma helpers ----------
__device__ __forceinline__ unsigned smem_u32(const void* p) {
    return (unsigned)__cvta_generic_to_shared(p);
}

__device__ __forceinline__ void ldsm_x4(unsigned& r0, unsigned& r1,
                                        unsigned& r2, unsigned& r3, unsigned a) {
    asm volatile("ldmatrix.sync.aligned.m8n8.x4.shared.b16 {%0,%1,%2,%3}, [%4];"
                 : "=r"(r0), "=r"(r1), "=r"(r2), "=r"(r3) : "r"(a));
}

__device__ __forceinline__ void ldsm_x4_t(unsigned& r0, unsigned& r1,
                                          unsigned& r2, unsigned& r3, unsigned a) {
    asm volatile("ldmatrix.sync.aligned.m8n8.x4.trans.shared.b16 {%0,%1,%2,%3}, [%4];"
                 : "=r"(r0), "=r"(r1), "=r"(r2), "=r"(r3) : "r"(a));
}

__device__ __forceinline__ void mma16816(float* d, unsigned a0, unsigned a1,
                                         unsigned a2, unsigned a3,
                                         unsigned b0, unsigned b1) {
    asm volatile("mma.sync.aligned.m16n8k16.row.col.f32.f16.f16.f32 "
                 "{%0,%1,%2,%3}, {%4,%5,%6,%7}, {%8,%9}, {%0,%1,%2,%3};"
                 : "+f"(d[0]), "+f"(d[1]), "+f"(d[2]), "+f"(d[3])
                 : "r"(a0), "r"(a1), "r"(a2), "r"(a3), "r"(b0), "r"(b1));
}

__device__ __forceinline__ unsigned h2u(__half2 h) {
    unsigned u;
    memcpy(&u, &h, 4);
    return u;
}

__device__ __forceinline__ void acc8(const uint4& v, float w, float* a) {
    float2 f0 = __half22float2(*(const __half2*)&v.x);
    float2 f1 = __half22float2(*(const __half2*)&v.y);
    float2 f2 = __half22float2(*(const __half2*)&v.z);
    float2 f3 = __half22float2(*(const __half2*)&v.w);
    a[0] = fmaf(f0.x, w, a[0]);
    a[1] = fmaf(f0.y, w, a[1]);
    a[2] = fmaf(f1.x, w, a[2]);
    a[3] = fmaf(f1.y, w, a[3]);
    a[4] = fmaf(f2.x, w, a[4]);
    a[5] = fmaf(f2.y, w, a[5]);
    a[6] = fmaf(f3.x, w, a[6]);
    a[7] = fmaf(f3.y, w, a[7]);
}

// ---------- init + degree histogram (deg pre-zeroed by memset) ----------
__global__ void k_init_hist(const float* __restrict__ ue,
                            const float* __restrict__ ie,
                            const float* __restrict__ Wsrc,
                            const float* __restrict__ tt,
                            const int* __restrict__ ui,
                            const int* __restrict__ ii,
                            float* __restrict__ out) {
    int i = blockIdx.x * blockDim.x + threadIdx.x;
    if (i < NN * HD) {
        int n = i >> 7;
        int j = i & 127;
        float v = (n < NU) ? ue[i] : ie[i - NU * HD];
        g_xhA[i] = __float2half(v);
        out[(long)n * OW + j] = v;
    }
    if (i < NL * HD * HD) {
        g_Wh[i] = __float2half(Wsrc[i]);
    }
    if (i < MAXT * HD) {
        g_tth[i] = __float2half(tt[i]);
    }
    if (i < NE) {
        atomicAdd(&g_deg[ui[i]], 1);
        atomicAdd(&g_deg[ii[i] + NU], 1);
    }
}

// ---------- single-block scan, warp-shuffle based ----------
// 1024 threads x 16 elements = 16384 per tile, 10 tiles, ~4 barriers/tile.
__global__ void __launch_bounds__(1024) k_monoscan() {
    __shared__ int wsum[32];
    __shared__ int carry_s;
    int tid = threadIdx.x;
    int lane = tid & 31;
    int wid = tid >> 5;
    if (tid == 0) carry_s = 0;
    __syncthreads();

    for (int base = 0; base < NN; base += 16384) {
        int i0 = base + tid * 16;
        int d[16];
        int local = 0;
        bool full_tile = (base + 16384 <= NN);
#pragma unroll
        for (int k = 0; k < 16; k += 4) {
            int4 v;
            if (full_tile) {
                v = *(const int4*)(g_deg + i0 + k);
            } else {
                v = make_int4(0, 0, 0, 0);
                if (i0 + k < NN) v.x = g_deg[i0 + k];
                if (i0 + k + 1 < NN) v.y = g_deg[i0 + k + 1];
                if (i0 + k + 2 < NN) v.z = g_deg[i0 + k + 2];
                if (i0 + k + 3 < NN) v.w = g_deg[i0 + k + 3];
            }
            d[k] = v.x; d[k + 1] = v.y; d[k + 2] = v.z; d[k + 3] = v.w;
            local += v.x + v.y + v.z + v.w;
        }
        // warp inclusive scan of local
        int inc = local;
#pragma unroll
        for (int off = 1; off < 32; off <<= 1) {
            int t = __shfl_up_sync(0xffffffffu, inc, off);
            if (lane >= off) inc += t;
        }
        if (lane == 31) wsum[wid] = inc;
        __syncthreads();
        if (wid == 0) {
            int s = wsum[lane];
#pragma unroll
            for (int off = 1; off < 32; off <<= 1) {
                int t = __shfl_up_sync(0xffffffffu, s, off);
                if (lane >= off) s += t;
            }
            wsum[lane] = s;
        }
        __syncthreads();
        int total = wsum[31];
        int run = carry_s + (wid ? wsum[wid - 1] : 0) + inc - local;
#pragma unroll
        for (int k = 0; k < 16; k++) {
            int i = i0 + k;
            if (i < NN) {
                g_rp[i] = run;
                g_cursor[i] = run;
                int dd = d[k];
                g_dinv[i] = rsqrtf((float)(dd > 1 ? dd : 1));
                run += dd;
            }
        }
        __syncthreads();
        if (tid == 0) carry_s += total;
        __syncthreads();
    }
    if (tid == 0) g_rp[NN] = NE2;
}

// ---------- CSR scatter (src index pre-scaled by 16 uint4 units) ----------
__global__ void k_scatter(const int* __restrict__ ui, const int* __restrict__ ii,
                          const int* __restrict__ ts) {
    int e = blockIdx.x * blockDim.x + threadIdx.x;
    if (e < NE) {
        int u = ui[e];
        int it = ii[e] + NU;
        int t = ts[e];
        float wu = g_dinv[u];
        float wi = g_dinv[it];
        int p = atomicAdd(&g_cursor[u], 1);
        g_edge2[p] = make_int2((it << 4) | (t << 22), __float_as_int(wi));
        int q = atomicAdd(&g_cursor[it], 1);
        g_edge2[q] = make_int2((u << 4) | (t << 22), __float_as_int(wu));
    }
}

// ---------- fused: aggregation + tensor-core GEMM + epilogue ----------
// 512 threads (16 warps), 2 blocks/SM. Block owns 128 node rows.
template <int FIRST>
__global__ void __launch_bounds__(512, 2) k_fused(int layer,
                                                  const __half* __restrict__ xin,
                                                  __half* __restrict__ xout,
                                                  const float* __restrict__ bias,
                                                  float* __restrict__ out,
                                                  int outoff) {
    extern __shared__ __half smem_dyn[];
    __half* As = smem_dyn;                         // [128][136]
    __half* Bs = smem_dyn + 128 * 136;             // [64][136]
    float*  bsm = (float*)(smem_dyn + 128 * 136 + 64 * 136);   // [128]
    float*  ssm = bsm + HD;                        // [128][2]

    const __half* Wh = g_Wh + layer * HD * HD;
    int tid = threadIdx.x;
    int lane = tid & 31;
    int warp = tid >> 5;
    int row0 = blockIdx.x * 128;

    if (tid < HD) {
        bsm[tid] = bias[tid];
    }

    // ---- phase 1: gather into As (32 half-warp chains per block) ----
    {
        int hw = tid >> 4;      // 0..31
        int sl = tid & 15;
        const uint4* xh4 = (const uint4*)xin;
        const uint4* tt4 = (const uint4*)g_tth;
        for (int batch = 0; batch < 4; batch++) {
            int r = batch * 32 + hw;
            int n = row0 + r;
            float a[8] = {0.f, 0.f, 0.f, 0.f, 0.f, 0.f, 0.f, 0.f};
            float at[8] = {0.f, 0.f, 0.f, 0.f, 0.f, 0.f, 0.f, 0.f};
            uint4 hv = make_uint4(0u, 0u, 0u, 0u);
            if (n < NN) {
                int beg = g_rp[n];
                int end = g_rp[n + 1];
                for (int e = beg; e < end; e++) {
                    int2 ed = __ldg(&g_edge2[e]);
                    float w = __int_as_float(ed.y);
                    uint4 v = __ldg(&xh4[(ed.x & 0x3FFFFF) + sl]);
                    acc8(v, w, a);
                    if (FIRST) {
                        uint4 tv = __ldg(&tt4[(((unsigned)ed.x >> 22) << 4) + sl]);
                        acc8(tv, w, at);
                    }
                }
                float wn = g_dinv[n];
                if (FIRST) {
                    uint4 th;
                    th.x = h2u(__floats2half2_rn(at[0], at[1]));
                    th.y = h2u(__floats2half2_rn(at[2], at[3]));
                    th.z = h2u(__floats2half2_rn(at[4], at[5]));
                    th.w = h2u(__floats2half2_rn(at[6], at[7]));
                    ((uint4*)(g_Th + (long)n * HD))[sl] = th;
                } else {
                    uint4 tv = ((const uint4*)(g_Th + (long)n * HD))[sl];
                    float2 t0 = __half22float2(*(const __half2*)&tv.x);
                    float2 t1 = __half22float2(*(const __half2*)&tv.y);
                    float2 t2 = __half22float2(*(const __half2*)&tv.z);
                    float2 t3 = __half22float2(*(const __half2*)&tv.w);
                    at[0] = t0.x; at[1] = t0.y;
                    at[2] = t1.x; at[3] = t1.y;
                    at[4] = t2.x; at[5] = t2.y;
                    at[6] = t3.x; at[7] = t3.y;
                }
                hv.x = h2u(__floats2half2_rn(wn * (a[0] + at[0]), wn * (a[1] + at[1])));
                hv.y = h2u(__floats2half2_rn(wn * (a[2] + at[2]), wn * (a[3] + at[3])));
                hv.z = h2u(__floats2half2_rn(wn * (a[4] + at[4]), wn * (a[5] + at[5])));
                hv.w = h2u(__floats2half2_rn(wn * (a[6] + at[6]), wn * (a[7] + at[7])));
            }
            *(uint4*)(&As[r * 136 + sl * 8]) = hv;
        }
    }

    // ---- phase 2: HMMA (warp: 16 rows x 64 cols) ----
    float acc[8][4];
#pragma unroll
    for (int t = 0; t < 8; t++) {
#pragma unroll
        for (int j = 0; j < 4; j++) {
            acc[t][j] = 0.f;
        }
    }

    int wr = (warp >> 1) * 16;     // row base within tile
    int cb = (warp & 1) * 64;      // col base
    for (int kc = 0; kc < 2; kc++) {
        for (int i = tid; i < 1024; i += 512) {
            int r = i >> 4;
            int q = i & 15;
            uint4 v = ((const uint4*)(Wh + (long)(kc * 64 + r) * HD))[q];
            *(uint4*)(&Bs[r * 136 + q * 8]) = v;
        }
        __syncthreads();
#pragma unroll
        for (int ks = 0; ks < 4; ks++) {
            int kk = kc * 64 + ks * 16;
            unsigned va0, va1, va2, va3;
            ldsm_x4(va0, va1, va2, va3,
                    smem_u32(&As[(wr + (lane & 15)) * 136 + kk + (lane >> 4) * 8]));
#pragma unroll
            for (int nt = 0; nt < 4; nt++) {
                unsigned vb0, vb1, vb2, vb3;
                ldsm_x4_t(vb0, vb1, vb2, vb3,
                          smem_u32(&Bs[(ks * 16 + (lane & 15)) * 136 + cb + nt * 16 + (lane >> 4) * 8]));
                mma16816(acc[nt * 2], va0, va1, va2, va3, vb0, vb1);
                mma16816(acc[nt * 2 + 1], va0, va1, va2, va3, vb2, vb3);
            }
        }
        __syncthreads();
    }

    // ---- phase 3: epilogue ----
    int qr = lane >> 2;
    int qc = lane & 3;
    int rl_loc = wr + qr;
    int rh_loc = rl_loc + 8;
    int cg = warp & 1;

    float ss0 = 0.f;
    float ss1 = 0.f;
#pragma unroll
    for (int t = 0; t < 8; t++) {
        int c0 = cb + t * 8 + qc * 2;
        float b0 = bsm[c0];
        float b1 = bsm[c0 + 1];
        float v0 = acc[t][0] + b0;
        float v1 = acc[t][1] + b1;
        float v2 = acc[t][2] + b0;
        float v3 = acc[t][3] + b1;
        v0 = (v0 >= 0.f) ? v0 : (SLOPE * v0);
        v1 = (v1 >= 0.f) ? v1 : (SLOPE * v1);
        v2 = (v2 >= 0.f) ? v2 : (SLOPE * v2);
        v3 = (v3 >= 0.f) ? v3 : (SLOPE * v3);
        acc[t][0] = v0;
        acc[t][1] = v1;
        acc[t][2] = v2;
        acc[t][3] = v3;
        ss0 = fmaf(v0, v0, ss0);
        ss0 = fmaf(v1, v1, ss0);
        ss1 = fmaf(v2, v2, ss1);
        ss1 = fmaf(v3, v3, ss1);
    }
    ss0 += __shfl_xor_sync(0xffffffffu, ss0, 1);
    ss0 += __shfl_xor_sync(0xffffffffu, ss0, 2);
    ss1 += __shfl_xor_sync(0xffffffffu, ss1, 1);
    ss1 += __shfl_xor_sync(0xffffffffu, ss1, 2);
    if (qc == 0) {
        ssm[rl_loc * 2 + cg] = ss0;
        ssm[rh_loc * 2 + cg] = ss1;
    }
    __syncthreads();
    float st0 = ssm[rl_loc * 2] + ssm[rl_loc * 2 + 1];
    float st1 = ssm[rh_loc * 2] + ssm[rh_loc * 2 + 1];
    float ri0 = 1.f / fmaxf(sqrtf(st0), 1e-12f);
    float ri1 = 1.f / fmaxf(sqrtf(st1), 1e-12f);

    int r_lo = row0 + rl_loc;
    int r_hi = row0 + rh_loc;
    if (r_lo < NN) {
        float* orow = out + (long)r_lo * OW + outoff;
        __half2* xrow = (__half2*)(xout + (long)r_lo * HD);
#pragma unroll
        for (int t = 0; t < 8; t++) {
            int c = cb + t * 8 + qc * 2;
            *(float2*)(orow + c) = make_float2(acc[t][0] * ri0, acc[t][1] * ri0);
            xrow[c >> 1] = __floats2half2_rn(acc[t][0], acc[t][1]);
        }
    }
    if (r_hi < NN) {
        float* orow = out + (long)r_hi * OW + outoff;
        __half2* xrow = (__half2*)(xout + (long)r_hi * HD);
#pragma unroll
        for (int t = 0; t < 8; t++) {
            int c = cb + t * 8 + qc * 2;
            *(float2*)(orow + c) = make_float2(acc[t][2] * ri1, acc[t][3] * ri1);
            xrow[c >> 1] = __floats2half2_rn(acc[t][2], acc[t][3]);
        }
    }
}

extern "C" void kernel_launch(void* const* d_in, const int* in_sizes, int n_in,
                              void* d_out, int out_size) {
    const float* user_embd  = (const float*)d_in[0];
    const float* item_embd  = (const float*)d_in[1];
    const float* time_table = (const float*)d_in[2];
    const float* Wsrc       = (const float*)d_in[3];
    const float* bsrc       = (const float*)d_in[4];
    const int*   user_idx   = (const int*)d_in[5];
    const int*   item_idx   = (const int*)d_in[6];
    const int*   time_seq   = (const int*)d_in[7];
    float* out = (float*)d_out;

    static __half* xbuf[2] = {nullptr, nullptr};
    static void* degp = nullptr;
    static int cfg = 0;
    if (!cfg) {
        cudaFuncSetAttribute(k_fused<0>, cudaFuncAttributeMaxDynamicSharedMemorySize,
                             FUSED_SMEM);
        cudaFuncSetAttribute(k_fused<1>, cudaFuncAttributeMaxDynamicSharedMemorySize,
                             FUSED_SMEM);
        cudaGetSymbolAddress((void**)&xbuf[0], g_xhA);
        cudaGetSymbolAddress((void**)&xbuf[1], g_xhB);
        cudaGetSymbolAddress(&degp, g_deg);
        cfg = 1;
    }

    cudaMemsetAsync(degp, 0, NN * sizeof(int));
    // launch 1: init + histogram
    k_init_hist<<<(NN * HD + 255) / 256, 256>>>(user_embd, item_embd, Wsrc,
                                                time_table, user_idx, item_idx,
                                                out);
    // launch 2: full scan in one block (shuffle-based, ~4 barriers/tile)
    k_monoscan<<<1, 1024>>>();
    // launch 3: CSR scatter
    k_scatter<<<(NE + 255) / 256, 256>>>(user_idx, item_idx, time_seq);
    // launch 4 (ncu window): fused layer 0
    k_fused<1><<<(NN + 127) / 128, 512, FUSED_SMEM>>>(0, xbuf[0], xbuf[1],
                                                      bsrc, out, HD);
    k_fused<0><<<(NN + 127) / 128, 512, FUSED_SMEM>>>(1, xbuf[1], xbuf[0],
                                                      bsrc + HD, out, 2 * HD);
    k_fused<0><<<(NN + 127) / 128, 512, FUSED_SMEM>>>(2, xbuf[0], xbuf[1],
                                                      bsrc + 2 * HD, out, 3 * HD);
}

// round 14
// speedup vs baseline: 1.4799x; 1.4799x over previous
#include <cuda_runtime.h>
#include <cuda_fp16.h>
#include <cuda_bf16.h>

#define NU 100000
#define NI 50000
#define NN 150000
#define HD 128
#define NE 1000000
#define NE2 2000000
#define NL 3
#define MAXT 512
#define SLOPE 0.2f
#define OW 512

#define SCAN_BS 1024
#define SCAN_NB 147

// As 128*136*2 + Bs(full W) 128*136*2 + bias 128*4 + ssm 256*4
#define FUSED_SMEM (34816 + 34816 + 512 + 1024)

// ---------- device scratch ----------
__device__ int    g_deg[NN];
__device__ int    g_rp[NN + 1];
__device__ int    g_cursor[NN];
__device__ float  g_dinv[NN];
__device__ int    g_partials[SCAN_NB + 1];
__device__ int2   g_edge2[NE2];
__device__ __half g_xhA[NN * HD];   // x buffer, parity 0
__device__ __half g_xhB[NN * HD];   // x buffer, parity 1
__device__ __half g_Th[NN * HD];    // time aggregation (fp16)
__device__ __half g_tth[MAXT * HD]; // fp16 time table
__device__ __half g_Wh[NL * HD * HD];

// ---------- mma helpers ----------
__device__ __forceinline__ unsigned smem_u32(const void* p) {
    return (unsigned)__cvta_generic_to_shared(p);
}

__device__ __forceinline__ void ldsm_x4(unsigned& r0, unsigned& r1,
                                        unsigned& r2, unsigned& r3, unsigned a) {
    asm volatile("ldmatrix.sync.aligned.m8n8.x4.shared.b16 {%0,%1,%2,%3}, [%4];"
                 : "=r"(r0), "=r"(r1), "=r"(r2), "=r"(r3) : "r"(a));
}

__device__ __forceinline__ void ldsm_x4_t(unsigned& r0, unsigned& r1,
                                          unsigned& r2, unsigned& r3, unsigned a) {
    asm volatile("ldmatrix.sync.aligned.m8n8.x4.trans.shared.b16 {%0,%1,%2,%3}, [%4];"
                 : "=r"(r0), "=r"(r1), "=r"(r2), "=r"(r3) : "r"(a));
}

__device__ __forceinline__ void mma16816(float* d, unsigned a0, unsigned a1,
                                         unsigned a2, unsigned a3,
                                         unsigned b0, unsigned b1) {
    asm volatile("mma.sync.aligned.m16n8k16.row.col.f32.f16.f16.f32 "
                 "{%0,%1,%2,%3}, {%4,%5,%6,%7}, {%8,%9}, {%0,%1,%2,%3};"
                 : "+f"(d[0]), "+f"(d[1]), "+f"(d[2]), "+f"(d[3])
                 : "r"(a0), "r"(a1), "r"(a2), "r"(a3), "r"(b0), "r"(b1));
}

__device__ __forceinline__ unsigned h2u(__half2 h) {
    unsigned u;
    memcpy(&u, &h, 4);
    return u;
}

__device__ __forceinline__ void acc8(const uint4& v, float w, float* a) {
    float2 f0 = __half22float2(*(const __half2*)&v.x);
    float2 f1 = __half22float2(*(const __half2*)&v.y);
    float2 f2 = __half22float2(*(const __half2*)&v.z);
    float2 f3 = __half22float2(*(const __half2*)&v.w);
    a[0] = fmaf(f0.x, w, a[0]);
    a[1] = fmaf(f0.y, w, a[1]);
    a[2] = fmaf(f1.x, w, a[2]);
    a[3] = fmaf(f1.y, w, a[3]);
    a[4] = fmaf(f2.x, w, a[4]);
    a[5] = fmaf(f2.y, w, a[5]);
    a[6] = fmaf(f3.x, w, a[6]);
    a[7] = fmaf(f3.y, w, a[7]);
}

// ---------- graph build (R11-proven structure) ----------
__global__ void k_hist(const int* __restrict__ ui, const int* __restrict__ ii) {
    int e = blockIdx.x * blockDim.x + threadIdx.x;
    if (e < NE) {
        atomicAdd(&g_deg[ui[e]], 1);
        atomicAdd(&g_deg[ii[e] + NU], 1);
    }
}

__global__ void k_scan1() {
    __shared__ int sh[SCAN_BS];
    int i = blockIdx.x * SCAN_BS + threadIdx.x;
    int v = (i < NN) ? g_deg[i] : 0;
    sh[threadIdx.x] = v;
    __syncthreads();
    for (int off = 1; off < SCAN_BS; off <<= 1) {
        int t = (threadIdx.x >= off) ? sh[threadIdx.x - off] : 0;
        __syncthreads();
        sh[threadIdx.x] += t;
        __syncthreads();
    }
    if (i < NN) g_rp[i] = sh[threadIdx.x] - v;
    if (threadIdx.x == SCAN_BS - 1) g_partials[blockIdx.x] = sh[SCAN_BS - 1];
}

__global__ void k_scan2() {
    __shared__ int sh[256];
    int i = threadIdx.x;
    int v = (i < SCAN_NB) ? g_partials[i] : 0;
    sh[i] = v;
    __syncthreads();
    for (int off = 1; off < 256; off <<= 1) {
        int t = (i >= off) ? sh[i - off] : 0;
        __syncthreads();
        sh[i] += t;
        __syncthreads();
    }
    if (i < SCAN_NB) g_partials[i] = sh[i] - v;
}

__global__ void k_scan3() {
    int i = blockIdx.x * blockDim.x + threadIdx.x;
    if (i < NN) {
        int v = g_rp[i] + g_partials[i / SCAN_BS];
        g_rp[i] = v;
        g_cursor[i] = v;
        int d = g_deg[i];
        g_dinv[i] = rsqrtf((float)(d > 1 ? d : 1));
    }
    if (i == 0) g_rp[NN] = NE2;
}

// src index pre-scaled by 16 (uint4 units); t in bits [22,31)
__global__ void k_scatter(const int* __restrict__ ui, const int* __restrict__ ii,
                          const int* __restrict__ ts) {
    int e = blockIdx.x * blockDim.x + threadIdx.x;
    if (e < NE) {
        int u = ui[e];
        int it = ii[e] + NU;
        int t = ts[e];
        float wu = g_dinv[u];
        float wi = g_dinv[it];
        int p = atomicAdd(&g_cursor[u], 1);
        g_edge2[p] = make_int2((it << 4) | (t << 22), __float_as_int(wi));
        int q = atomicAdd(&g_cursor[it], 1);
        g_edge2[q] = make_int2((u << 4) | (t << 22), __float_as_int(wu));
    }
}

// ---------- init ----------
__global__ void k_init(const float* __restrict__ ue, const float* __restrict__ ie,
                       const float* __restrict__ Wsrc, const float* __restrict__ tt,
                       float* __restrict__ out) {
    int i = blockIdx.x * blockDim.x + threadIdx.x;
    if (i < NN * HD) {
        int n = i >> 7;
        int j = i & 127;
        float v = (n < NU) ? ue[i] : ie[i - NU * HD];
        g_xhA[i] = __float2half(v);
        out[(long)n * OW + j] = v;
    }
    if (i < NL * HD * HD) {
        g_Wh[i] = __float2half(Wsrc[i]);
    }
    if (i < MAXT * HD) {
        g_tth[i] = __float2half(tt[i]);
    }
}

// ---------- fused: aggregation + tensor-core GEMM + epilogue ----------
// 512 threads (16 warps), 2 blocks/SM. Block owns 128 node rows.
// Full W tile resident in smem (loaded before gather); ONE sync between
// gather and MMA.
template <int FIRST>
__global__ void __launch_bounds__(512, 2) k_fused(int layer,
                                                  const __half* __restrict__ xin,
                                                  __half* __restrict__ xout,
                                                  const float* __restrict__ bias,
                                                  float* __restrict__ out,
                                                  int outoff) {
    extern __shared__ __half smem_dyn[];
    __half* As = smem_dyn;                         // [128][136]
    __half* Bs = smem_dyn + 128 * 136;             // [128][136] full W
    float*  bsm = (float*)(smem_dyn + 2 * 128 * 136);   // [128]
    float*  ssm = bsm + HD;                        // [128][2]

    const __half* Wh = g_Wh + layer * HD * HD;
    int tid = threadIdx.x;
    int lane = tid & 31;
    int warp = tid >> 5;
    int row0 = blockIdx.x * 128;

    if (tid < HD) {
        bsm[tid] = bias[tid];
    }

    // ---- load full W into Bs (before gather; covered by the single sync) ----
    for (int i = tid; i < 2048; i += 512) {
        int r = i >> 4;
        int q = i & 15;
        uint4 v = ((const uint4*)(Wh + (long)r * HD))[q];
        *(uint4*)(&Bs[r * 136 + q * 8]) = v;
    }

    // ---- phase 1: gather into As (32 half-warp chains per block) ----
    {
        int hw = tid >> 4;      // 0..31
        int sl = tid & 15;
        const uint4* xh4 = (const uint4*)xin;
        const uint4* tt4 = (const uint4*)g_tth;
        for (int batch = 0; batch < 4; batch++) {
            int r = batch * 32 + hw;
            int n = row0 + r;
            float a[8] = {0.f, 0.f, 0.f, 0.f, 0.f, 0.f, 0.f, 0.f};
            float at[8] = {0.f, 0.f, 0.f, 0.f, 0.f, 0.f, 0.f, 0.f};
            uint4 hv = make_uint4(0u, 0u, 0u, 0u);
            if (n < NN) {
                int beg = g_rp[n];
                int end = g_rp[n + 1];
                for (int e = beg; e < end; e++) {
                    int2 ed = __ldg(&g_edge2[e]);
                    float w = __int_as_float(ed.y);
                    uint4 v = __ldg(&xh4[(ed.x & 0x3FFFFF) + sl]);
                    acc8(v, w, a);
                    if (FIRST) {
                        uint4 tv = __ldg(&tt4[((((unsigned)ed.x) >> 22) << 4) + sl]);
                        acc8(tv, w, at);
                    }
                }
                float wn = g_dinv[n];
                if (FIRST) {
                    uint4 th;
                    th.x = h2u(__floats2half2_rn(at[0], at[1]));
                    th.y = h2u(__floats2half2_rn(at[2], at[3]));
                    th.z = h2u(__floats2half2_rn(at[4], at[5]));
                    th.w = h2u(__floats2half2_rn(at[6], at[7]));
                    ((uint4*)(g_Th + (long)n * HD))[sl] = th;
                } else {
                    uint4 tv = ((const uint4*)(g_Th + (long)n * HD))[sl];
                    float2 t0 = __half22float2(*(const __half2*)&tv.x);
                    float2 t1 = __half22float2(*(const __half2*)&tv.y);
                    float2 t2 = __half22float2(*(const __half2*)&tv.z);
                    float2 t3 = __half22float2(*(const __half2*)&tv.w);
                    at[0] = t0.x; at[1] = t0.y;
                    at[2] = t1.x; at[3] = t1.y;
                    at[4] = t2.x; at[5] = t2.y;
                    at[6] = t3.x; at[7] = t3.y;
                }
                hv.x = h2u(__floats2half2_rn(wn * (a[0] + at[0]), wn * (a[1] + at[1])));
                hv.y = h2u(__floats2half2_rn(wn * (a[2] + at[2]), wn * (a[3] + at[3])));
                hv.z = h2u(__floats2half2_rn(wn * (a[4] + at[4]), wn * (a[5] + at[5])));
                hv.w = h2u(__floats2half2_rn(wn * (a[6] + at[6]), wn * (a[7] + at[7])));
            }
            *(uint4*)(&As[r * 136 + sl * 8]) = hv;
        }
    }

    __syncthreads();   // the ONE barrier: As + Bs ready

    // ---- phase 2: HMMA (warp: 16 rows x 64 cols), K=128 straight through ----
    float acc[8][4];
#pragma unroll
    for (int t = 0; t < 8; t++) {
#pragma unroll
        for (int j = 0; j < 4; j++) {
            acc[t][j] = 0.f;
        }
    }

    int wr = (warp >> 1) * 16;     // row base within tile
    int cb = (warp & 1) * 64;      // col base
#pragma unroll
    for (int ks = 0; ks < 8; ks++) {
        int kk = ks * 16;
        unsigned va0, va1, va2, va3;
        ldsm_x4(va0, va1, va2, va3,
                smem_u32(&As[(wr + (lane & 15)) * 136 + kk + (lane >> 4) * 8]));
#pragma unroll
        for (int nt = 0; nt < 4; nt++) {
            unsigned vb0, vb1, vb2, vb3;
            ldsm_x4_t(vb0, vb1, vb2, vb3,
                      smem_u32(&Bs[(kk + (lane & 15)) * 136 + cb + nt * 16 + (lane >> 4) * 8]));
            mma16816(acc[nt * 2], va0, va1, va2, va3, vb0, vb1);
            mma16816(acc[nt * 2 + 1], va0, va1, va2, va3, vb2, vb3);
        }
    }

    // ---- phase 3: epilogue ----
    int qr = lane >> 2;
    int qc = lane & 3;
    int rl_loc = wr + qr;
    int rh_loc = rl_loc + 8;
    int cg = warp & 1;

    float ss0 = 0.f;
    float ss1 = 0.f;
#pragma unroll
    for (int t = 0; t < 8; t++) {
        int c0 = cb + t * 8 + qc * 2;
        float b0 = bsm[c0];
        float b1 = bsm[c0 + 1];
        float v0 = acc[t][0] + b0;
        float v1 = acc[t][1] + b1;
        float v2 = acc[t][2] + b0;
        float v3 = acc[t][3] + b1;
        v0 = (v0 >= 0.f) ? v0 : (SLOPE * v0);
        v1 = (v1 >= 0.f) ? v1 : (SLOPE * v1);
        v2 = (v2 >= 0.f) ? v2 : (SLOPE * v2);
        v3 = (v3 >= 0.f) ? v3 : (SLOPE * v3);
        acc[t][0] = v0;
        acc[t][1] = v1;
        acc[t][2] = v2;
        acc[t][3] = v3;
        ss0 = fmaf(v0, v0, ss0);
        ss0 = fmaf(v1, v1, ss0);
        ss1 = fmaf(v2, v2, ss1);
        ss1 = fmaf(v3, v3, ss1);
    }
    ss0 += __shfl_xor_sync(0xffffffffu, ss0, 1);
    ss0 += __shfl_xor_sync(0xffffffffu, ss0, 2);
    ss1 += __shfl_xor_sync(0xffffffffu, ss1, 1);
    ss1 += __shfl_xor_sync(0xffffffffu, ss1, 2);
    if (qc == 0) {
        ssm[rl_loc * 2 + cg] = ss0;
        ssm[rh_loc * 2 + cg] = ss1;
    }
    __syncthreads();
    float st0 = ssm[rl_loc * 2] + ssm[rl_loc * 2 + 1];
    float st1 = ssm[rh_loc * 2] + ssm[rh_loc * 2 + 1];
    float ri0 = 1.f / fmaxf(sqrtf(st0), 1e-12f);
    float ri1 = 1.f / fmaxf(sqrtf(st1), 1e-12f);

    int r_lo = row0 + rl_loc;
    int r_hi = row0 + rh_loc;
    if (r_lo < NN) {
        float* orow = out + (long)r_lo * OW + outoff;
        __half2* xrow = (__half2*)(xout + (long)r_lo * HD);
#pragma unroll
        for (int t = 0; t < 8; t++) {
            int c = cb + t * 8 + qc * 2;
            *(float2*)(orow + c) = make_float2(acc[t][0] * ri0, acc[t][1] * ri0);
            xrow[c >> 1] = __floats2half2_rn(acc[t][0], acc[t][1]);
        }
    }
    if (r_hi < NN) {
        float* orow = out + (long)r_hi * OW + outoff;
        __half2* xrow = (__half2*)(xout + (long)r_hi * HD);
#pragma unroll
        for (int t = 0; t < 8; t++) {
            int c = cb + t * 8 + qc * 2;
            *(float2*)(orow + c) = make_float2(acc[t][2] * ri1, acc[t][3] * ri1);
            xrow[c >> 1] = __floats2half2_rn(acc[t][2], acc[t][3]);
        }
    }
}

extern "C" void kernel_launch(void* const* d_in, const int* in_sizes, int n_in,
                              void* d_out, int out_size) {
    const float* user_embd  = (const float*)d_in[0];
    const float* item_embd  = (const float*)d_in[1];
    const float* time_table = (const float*)d_in[2];
    const float* Wsrc       = (const float*)d_in[3];
    const float* bsrc       = (const float*)d_in[4];
    const int*   user_idx   = (const int*)d_in[5];
    const int*   item_idx   = (const int*)d_in[6];
    const int*   time_seq   = (const int*)d_in[7];
    float* out = (float*)d_out;

    static __half* xbuf[2] = {nullptr, nullptr};
    static void* degp = nullptr;
    static int cfg = 0;
    if (!cfg) {
        cudaFuncSetAttribute(k_fused<0>, cudaFuncAttributeMaxDynamicSharedMemorySize,
                             FUSED_SMEM);
        cudaFuncSetAttribute(k_fused<1>, cudaFuncAttributeMaxDynamicSharedMemorySize,
                             FUSED_SMEM);
        cudaGetSymbolAddress((void**)&xbuf[0], g_xhA);
        cudaGetSymbolAddress((void**)&xbuf[1], g_xhB);
        cudaGetSymbolAddress(&degp, g_deg);
        cfg = 1;
    }

    cudaMemsetAsync(degp, 0, NN * sizeof(int));
    k_hist<<<(NE + 255) / 256, 256>>>(user_idx, item_idx);
    k_scan1<<<SCAN_NB, SCAN_BS>>>();
    k_scan2<<<1, 256>>>();
    k_scan3<<<(NN + 255) / 256, 256>>>();
    k_scatter<<<(NE + 255) / 256, 256>>>(user_idx, item_idx, time_seq);

    k_init<<<(NN * HD + 255) / 256, 256>>>(user_embd, item_embd, Wsrc,
                                           time_table, out);

    k_fused<1><<<(NN + 127) / 128, 512, FUSED_SMEM>>>(0, xbuf[0], xbuf[1],
                                                      bsrc, out, HD);
    k_fused<0><<<(NN + 127) / 128, 512, FUSED_SMEM>>>(1, xbuf[1], xbuf[0],
                                                      bsrc + HD, out, 2 * HD);
    k_fused<0><<<(NN + 127) / 128, 512, FUSED_SMEM>>>(2, xbuf[0], xbuf[1],
                                                      bsrc + 2 * HD, out, 3 * HD);
}